// round 8
// baseline (speedup 1.0000x reference)
#include <cuda_runtime.h>
#include <cuda_bf16.h>
#include <cstdint>

#define NN   100000
#define EE   1600000
#define IND  128
#define HIDD 256
#define OUTD 64
#define NB_SCAN 196   // ceil(NN/512)

// ---------------- scratch (device globals: allocation-free rule) -------------
__device__ int   g_src[EE];
__device__ int   g_dst[EE];
__device__ int   g_eidx[EE];
__device__ int   g_count[NN];
__device__ int   g_cursor[NN];
__device__ int   g_bsum[NB_SCAN];
__device__ int   g_off[NN + 1];
__device__ float g_inv[NN];
__device__ float g_pq[NN * (2 * OUTD)];
__device__ int   g_is64;

// pre-split bf16 operands (hi/lo error-compensation pairs)
__device__ __align__(16) __nv_bfloat16 g_a1h[NN * 256];   // [mean|x] hi
__device__ __align__(16) __nv_bfloat16 g_a1l[NN * 256];   // [mean|x] lo
__device__ __align__(16) __nv_bfloat16 g_hh[NN * 256];    // h hi
__device__ __align__(16) __nv_bfloat16 g_hl[NN * 256];    // h lo
__device__ __align__(16) __nv_bfloat16 g_w1h[256 * 256];
__device__ __align__(16) __nv_bfloat16 g_w1l[256 * 256];
__device__ __align__(16) __nv_bfloat16 g_w2h[128 * 256];
__device__ __align__(16) __nv_bfloat16 g_w2l[128 * 256];

// ---------------- helpers -----------------------------------------------------
__device__ __forceinline__ uint32_t smem_u32(const void* p) {
    uint32_t a;
    asm("{ .reg .u64 t; cvta.to.shared.u64 t, %1; cvt.u32.u64 %0, t; }"
        : "=r"(a) : "l"(p));
    return a;
}
__device__ __forceinline__ void ldsm4(uint32_t* r, uint32_t addr) {
    asm volatile("ldmatrix.sync.aligned.m8n8.x4.shared.b16 {%0,%1,%2,%3}, [%4];"
                 : "=r"(r[0]), "=r"(r[1]), "=r"(r[2]), "=r"(r[3]) : "r"(addr));
}
__device__ __forceinline__ void mma_bf16(float* d, const uint32_t* a,
                                         uint32_t b0, uint32_t b1) {
    asm volatile(
        "mma.sync.aligned.m16n8k16.row.col.f32.bf16.bf16.f32 "
        "{%0,%1,%2,%3}, {%4,%5,%6,%7}, {%8,%9}, {%0,%1,%2,%3};"
        : "+f"(d[0]), "+f"(d[1]), "+f"(d[2]), "+f"(d[3])
        : "r"(a[0]), "r"(a[1]), "r"(a[2]), "r"(a[3]), "r"(b0), "r"(b1));
}
// split v into hi (bf16) and lo (bf16 of residual)
__device__ __forceinline__ void bsplit(float v, __nv_bfloat16& h, __nv_bfloat16& l) {
    h = __float2bfloat16(v);
    l = __float2bfloat16(v - __bfloat162float(h));
}

// ---------------- index dtype detection ---------------------------------------
__global__ void k_detect(const void* __restrict__ ei) {
    __shared__ int s_any;
    if (threadIdx.x == 0) s_any = 0;
    __syncthreads();
    const uint2* p = (const uint2*)ei;
    unsigned any = 0;
    for (int i = threadIdx.x; i < 2048; i += blockDim.x) any |= p[i].y;
    if (any) atomicOr(&s_any, 1);
    __syncthreads();
    if (threadIdx.x == 0) g_is64 = (s_any == 0) ? 1 : 0;
}

__global__ void k_zero_cnt() {
    int t = blockIdx.x * blockDim.x + threadIdx.x;
    if (t < NN) { g_count[t] = 0; g_cursor[t] = 0; }
}

__global__ void k_convert(const void* __restrict__ ei) {
    int t = blockIdx.x * blockDim.x + threadIdx.x;
    if (t >= 2 * EE) return;
    int v;
    if (g_is64) v = (int)((const long long*)ei)[t];
    else        v = ((const int*)ei)[t];
    if (t < EE) g_src[t] = v;
    else { g_dst[t - EE] = v; atomicAdd(&g_count[v], 1); }
}

// ---------------- exclusive scan of g_count -> g_off --------------------------
__global__ void k_s1() {
    int t = blockIdx.x * 512 + threadIdx.x;
    int v = (t < NN) ? g_count[t] : 0;
    __shared__ int sw[16];
    int wid = threadIdx.x >> 5, lid = threadIdx.x & 31;
    int s = v;
#pragma unroll
    for (int o = 16; o > 0; o >>= 1) s += __shfl_down_sync(0xffffffff, s, o);
    if (lid == 0) sw[wid] = s;
    __syncthreads();
    if (wid == 0) {
        int x = (lid < 16) ? sw[lid] : 0;
#pragma unroll
        for (int o = 16; o > 0; o >>= 1) x += __shfl_down_sync(0xffffffff, x, o);
        if (lid == 0) g_bsum[blockIdx.x] = x;
    }
}
__global__ void k_s2() {
    if (threadIdx.x == 0) {
        int run = 0;
        for (int i = 0; i < NB_SCAN; i++) { int v = g_bsum[i]; g_bsum[i] = run; run += v; }
        g_off[NN] = run;
    }
}
__global__ void k_s3() {
    __shared__ int sm[512];
    int t = blockIdx.x * 512 + threadIdx.x;
    int v = (t < NN) ? g_count[t] : 0;
    sm[threadIdx.x] = v;
    __syncthreads();
#pragma unroll
    for (int o = 1; o < 512; o <<= 1) {
        int tmp = (threadIdx.x >= o) ? sm[threadIdx.x - o] : 0;
        __syncthreads();
        sm[threadIdx.x] += tmp;
        __syncthreads();
    }
    if (t < NN) g_off[t] = sm[threadIdx.x] - v + g_bsum[blockIdx.x];
}

__global__ void k_build() {
    int t = blockIdx.x * blockDim.x + threadIdx.x;
    if (t >= EE) return;
    int d = g_dst[t];
    int p = g_off[d] + atomicAdd(&g_cursor[d], 1);
    g_eidx[p] = g_src[t];
}

// ---------------- weight split (runs once, tiny) -------------------------------
__global__ void k_splitw(const float* __restrict__ W1l, const float* __restrict__ W1r,
                         const float* __restrict__ W2l, const float* __restrict__ W2r) {
    int t = blockIdx.x * blockDim.x + threadIdx.x;
    if (t < 256 * 256) {
        int row = t >> 8, k = t & 255;
        float v = (k < 128) ? W1l[row * 128 + k] : W1r[row * 128 + (k - 128)];
        bsplit(v, g_w1h[t], g_w1l[t]);
    } else if (t < 256 * 256 + 128 * 256) {
        int u = t - 256 * 256;
        int row = u >> 8, k = u & 255;
        float v = (row < 64) ? W2l[row * 256 + k] : W2r[(row - 64) * 256 + k];
        bsplit(v, g_w2h[u], g_w2l[u]);
    }
}

// ---------------- layer-1 segmented mean + split: warp per node ----------------
__global__ void k_reduce1(const float* __restrict__ x) {
    int wgl = (blockIdx.x * blockDim.x + threadIdx.x) >> 5;
    int lane = threadIdx.x & 31;
    if (wgl >= NN) return;
    int beg = g_off[wgl], end = g_off[wgl + 1];
    float4 acc = make_float4(0.f, 0.f, 0.f, 0.f);
    for (int base = beg; base < end; base += 32) {
        int rem = end - base;
        int eid = (lane < rem) ? g_eidx[base + lane] : 0;
        int cnt = rem < 32 ? rem : 32;
#pragma unroll 4
        for (int j = 0; j < cnt; j++) {
            int s = __shfl_sync(0xffffffff, eid, j);
            float4 v = ((const float4*)x)[s * 32 + lane];
            acc.x += v.x; acc.y += v.y; acc.z += v.z; acc.w += v.w;
        }
    }
    float inv = 1.0f / fmaxf((float)(end - beg), 1.0f);
    acc.x *= inv; acc.y *= inv; acc.z *= inv; acc.w *= inv;
    if (lane == 0) g_inv[wgl] = inv;

    // split mean -> cols lane*4..+3 of [mean|x] row
    __nv_bfloat16 h[4], l[4];
    bsplit(acc.x, h[0], l[0]); bsplit(acc.y, h[1], l[1]);
    bsplit(acc.z, h[2], l[2]); bsplit(acc.w, h[3], l[3]);
    *(ushort4*)(g_a1h + wgl * 256 + lane * 4) = *(ushort4*)h;
    *(ushort4*)(g_a1l + wgl * 256 + lane * 4) = *(ushort4*)l;
    // split own x row -> cols 128+lane*4
    float4 xv = ((const float4*)x)[wgl * 32 + lane];
    bsplit(xv.x, h[0], l[0]); bsplit(xv.y, h[1], l[1]);
    bsplit(xv.z, h[2], l[2]); bsplit(xv.w, h[3], l[3]);
    *(ushort4*)(g_a1h + wgl * 256 + 128 + lane * 4) = *(ushort4*)h;
    *(ushort4*)(g_a1l + wgl * 256 + 128 + lane * 4) = *(ushort4*)l;
}

// ======================= mma.sync bf16x2-split GEMM ==========================
// MODE 0: h = relu(A1 @ W1^T + b1)   A1 = pre-split [mean|x], N=256 (grid.y=2)
// MODE 1: pq = H @ W2^T              H  = pre-split h,        N=128 (grid.y=1)
// All operands pre-split: staging = pure uint4 copy into swizzled smem.
template <int MODE>
__global__ __launch_bounds__(256) void k_gemm_mma(const float* __restrict__ bias)
{
    extern __shared__ char smem[];
    const int OF_AH = 0, OF_AL = 16384, OF_BH = 32768, OF_BL = 49152;
    const uint32_t sb = smem_u32(smem);

    const int tid  = threadIdx.x;
    const int wid  = tid >> 5;
    const int lane = tid & 31;
    const int wm   = wid & 3;
    const int wn   = wid >> 2;
    const int m0   = blockIdx.x * 128;
    const int j0   = blockIdx.y * 128;

    const __nv_bfloat16* Ah = (MODE == 0) ? g_a1h : g_hh;
    const __nv_bfloat16* Al = (MODE == 0) ? g_a1l : g_hl;
    const __nv_bfloat16* Bh = (MODE == 0) ? g_w1h : g_w2h;
    const __nv_bfloat16* Bl = (MODE == 0) ? g_w1l : g_w2l;

    float acc[2][8][4];
#pragma unroll
    for (int a = 0; a < 2; a++)
#pragma unroll
        for (int b = 0; b < 8; b++)
#pragma unroll
            for (int c = 0; c < 4; c++) acc[a][b][c] = 0.f;

    const int r8   = lane & 7;
    const int subm = lane >> 3;
    const uint4 zero4 = make_uint4(0, 0, 0, 0);

    for (int kt = 0; kt < 256; kt += 64) {
        // ---- stage A: 128 rows x 64 k (8 chunks of 16B), hi + lo --------------
#pragma unroll
        for (int i = 0; i < 4; i++) {
            int idx = tid + i * 256;          // 0..1023
            int row = idx >> 3;               // 0..127
            int c8  = idx & 7;                // 16B chunk along k
            int gr  = m0 + row;
            uint32_t byte = (uint32_t)(row * 128 + ((c8 ^ (row & 7)) * 16));
            uint4 vh = zero4, vl = zero4;
            if (gr < NN) {
                vh = *(const uint4*)(Ah + gr * 256 + kt + c8 * 8);
                vl = *(const uint4*)(Al + gr * 256 + kt + c8 * 8);
            }
            *(uint4*)(smem + OF_AH + byte) = vh;
            *(uint4*)(smem + OF_AL + byte) = vl;
        }
        // ---- stage B: 128 rows x 64 k ------------------------------------------
#pragma unroll
        for (int i = 0; i < 4; i++) {
            int idx = tid + i * 256;
            int row = idx >> 3;
            int c8  = idx & 7;
            uint32_t byte = (uint32_t)(row * 128 + ((c8 ^ (row & 7)) * 16));
            *(uint4*)(smem + OF_BH + byte) = *(const uint4*)(Bh + (j0 + row) * 256 + kt + c8 * 8);
            *(uint4*)(smem + OF_BL + byte) = *(const uint4*)(Bl + (j0 + row) * 256 + kt + c8 * 8);
        }
        __syncthreads();

#pragma unroll
        for (int ks = 0; ks < 4; ks++) {
            const int cb = ks * 2;
            uint32_t ah[2][4], al[2][4];
#pragma unroll
            for (int tm = 0; tm < 2; tm++) {
                int arow = wm * 32 + tm * 16 + (subm & 1) * 8 + r8;
                int achk = cb + (subm >> 1);
                uint32_t ab = (uint32_t)(arow * 128 + ((achk ^ (arow & 7)) * 16));
                ldsm4(ah[tm], sb + OF_AH + ab);
                ldsm4(al[tm], sb + OF_AL + ab);
            }
            uint32_t bh[16], bl[16];
#pragma unroll
            for (int g = 0; g < 4; g++) {
                int brow = wn * 64 + g * 16 + (subm >> 1) * 8 + r8;
                int bchk = cb + (subm & 1);
                uint32_t bb = (uint32_t)(brow * 128 + ((bchk ^ (brow & 7)) * 16));
                ldsm4(&bh[g * 4], sb + OF_BH + bb);
                ldsm4(&bl[g * 4], sb + OF_BL + bb);
            }
#pragma unroll
            for (int tm = 0; tm < 2; tm++)
#pragma unroll
                for (int tn = 0; tn < 8; tn++) {
                    mma_bf16(acc[tm][tn], ah[tm], bh[tn * 2], bh[tn * 2 + 1]);
                    mma_bf16(acc[tm][tn], ah[tm], bl[tn * 2], bl[tn * 2 + 1]);
                    mma_bf16(acc[tm][tn], al[tm], bh[tn * 2], bh[tn * 2 + 1]);
                }
        }
        __syncthreads();
    }

    // ---- epilogue: MODE0 writes split h; MODE1 writes fp32 pq -----------------
    const int qrow = lane >> 2;
    const int qcol = (lane & 3) * 2;
#pragma unroll
    for (int tm = 0; tm < 2; tm++) {
#pragma unroll
        for (int half = 0; half < 2; half++) {
            int gr = m0 + wm * 32 + tm * 16 + half * 8 + qrow;
            if (gr >= NN) continue;
#pragma unroll
            for (int tn = 0; tn < 8; tn++) {
                int gc = j0 + wn * 64 + tn * 8 + qcol;
                float v0 = acc[tm][tn][half * 2 + 0];
                float v1 = acc[tm][tn][half * 2 + 1];
                if (MODE == 0) {
                    v0 = fmaxf(v0 + bias[gc], 0.f);
                    v1 = fmaxf(v1 + bias[gc + 1], 0.f);
                    __nv_bfloat16 h0, l0, h1, l1;
                    bsplit(v0, h0, l0);
                    bsplit(v1, h1, l1);
                    __nv_bfloat16 hp[2] = {h0, h1}, lp[2] = {l0, l1};
                    *(uint32_t*)(g_hh + gr * 256 + gc) = *(uint32_t*)hp;
                    *(uint32_t*)(g_hl + gr * 256 + gc) = *(uint32_t*)lp;
                } else {
                    *(float2*)(g_pq + gr * (2 * OUTD) + gc) = make_float2(v0, v1);
                }
            }
        }
    }
}

// ---------------- layer-2 segmented mean + epilogue: warp per node ------------
__global__ void k_reduce2(const float* __restrict__ b2, float* __restrict__ out) {
    int wgl = (blockIdx.x * blockDim.x + threadIdx.x) >> 5;
    int lane = threadIdx.x & 31;
    if (wgl >= NN) return;
    int beg = g_off[wgl], end = g_off[wgl + 1];
    float2 acc = make_float2(0.f, 0.f);
    for (int base = beg; base < end; base += 32) {
        int rem = end - base;
        int eid = (lane < rem) ? g_eidx[base + lane] : 0;
        int cnt = rem < 32 ? rem : 32;
#pragma unroll 4
        for (int j = 0; j < cnt; j++) {
            int s = __shfl_sync(0xffffffff, eid, j);
            float2 v = ((const float2*)g_pq)[s * 64 + lane];   // p half
            acc.x += v.x; acc.y += v.y;
        }
    }
    float inv = g_inv[wgl];
    float2 q  = ((const float2*)g_pq)[wgl * 64 + 32 + lane];   // q half
    float2 bb = ((const float2*)b2)[lane];
    float2 r;
    r.x = fmaf(acc.x, inv, bb.x) + q.x;
    r.y = fmaf(acc.y, inv, bb.y) + q.y;
    ((float2*)out)[wgl * 32 + lane] = r;
}

// ---------------- launch ------------------------------------------------------
extern "C" void kernel_launch(void* const* d_in, const int* in_sizes, int n_in,
                              void* d_out, int out_size) {
    const float* x   = (const float*)d_in[0];
    const void*  ei  = d_in[1];
    const float* W1l = (const float*)d_in[2];
    const float* b1  = (const float*)d_in[3];
    const float* W1r = (const float*)d_in[4];
    const float* W2l = (const float*)d_in[5];
    const float* b2  = (const float*)d_in[6];
    const float* W2r = (const float*)d_in[7];
    float* out = (float*)d_out;

    const int SMEM = 65536;
    cudaFuncSetAttribute(k_gemm_mma<0>,
                         cudaFuncAttributeMaxDynamicSharedMemorySize, SMEM);
    cudaFuncSetAttribute(k_gemm_mma<1>,
                         cudaFuncAttributeMaxDynamicSharedMemorySize, SMEM);

    k_detect<<<1, 256>>>(ei);
    k_zero_cnt<<<(NN + 255) / 256, 256>>>();
    k_convert<<<(2 * EE + 255) / 256, 256>>>(ei);
    k_splitw<<<(256 * 256 + 128 * 256 + 255) / 256, 256>>>(W1l, W1r, W2l, W2r);

    k_s1<<<NB_SCAN, 512>>>();
    k_s2<<<1, 32>>>();
    k_s3<<<NB_SCAN, 512>>>();
    k_build<<<(EE + 255) / 256, 256>>>();

    k_reduce1<<<(NN * 32 + 255) / 256, 256>>>(x);

    const int MT = (NN + 127) / 128;   // 782
    k_gemm_mma<0><<<dim3(MT, 2), 256, SMEM>>>(b1);
    k_gemm_mma<1><<<dim3(MT, 1), 256, SMEM>>>(b1);

    k_reduce2<<<(NN * 32 + 255) / 256, 256>>>(b2, out);
}

// round 9
// speedup vs baseline: 1.3228x; 1.3228x over previous
#include <cuda_runtime.h>
#include <cuda_bf16.h>
#include <cstdint>

#define NN   100000
#define EE   1600000
#define IND  128
#define HIDD 256
#define OUTD 64
#define NB_SCAN 196   // ceil(NN/512)

// ---------------- scratch (device globals: allocation-free rule) -------------
__device__ int   g_src[EE];
__device__ int   g_dst[EE];
__device__ int   g_eidx[EE];
__device__ int   g_count[NN];
__device__ int   g_cursor[NN];
__device__ int   g_bsum[NB_SCAN];
__device__ int   g_off[NN + 1];
__device__ float g_inv[NN];
__device__ float g_pq[NN * (2 * OUTD)];
__device__ int   g_is64;

// pre-split bf16 operands (hi/lo error-compensation pairs)
__device__ __align__(16) __nv_bfloat16 g_a1h[NN * 256];   // [mean|x] hi
__device__ __align__(16) __nv_bfloat16 g_a1l[NN * 256];   // [mean|x] lo
__device__ __align__(16) __nv_bfloat16 g_hh[NN * 256];    // h hi
__device__ __align__(16) __nv_bfloat16 g_hl[NN * 256];    // h lo
__device__ __align__(16) __nv_bfloat16 g_w1h[256 * 256];
__device__ __align__(16) __nv_bfloat16 g_w1l[256 * 256];
__device__ __align__(16) __nv_bfloat16 g_w2h[128 * 256];
__device__ __align__(16) __nv_bfloat16 g_w2l[128 * 256];

// ---------------- helpers -----------------------------------------------------
__device__ __forceinline__ uint32_t smem_u32(const void* p) {
    uint32_t a;
    asm("{ .reg .u64 t; cvta.to.shared.u64 t, %1; cvt.u32.u64 %0, t; }"
        : "=r"(a) : "l"(p));
    return a;
}
__device__ __forceinline__ void ldsm4(uint32_t* r, uint32_t addr) {
    asm volatile("ldmatrix.sync.aligned.m8n8.x4.shared.b16 {%0,%1,%2,%3}, [%4];"
                 : "=r"(r[0]), "=r"(r[1]), "=r"(r[2]), "=r"(r[3]) : "r"(addr));
}
__device__ __forceinline__ void mma_bf16(float* d, const uint32_t* a,
                                         uint32_t b0, uint32_t b1) {
    asm volatile(
        "mma.sync.aligned.m16n8k16.row.col.f32.bf16.bf16.f32 "
        "{%0,%1,%2,%3}, {%4,%5,%6,%7}, {%8,%9}, {%0,%1,%2,%3};"
        : "+f"(d[0]), "+f"(d[1]), "+f"(d[2]), "+f"(d[3])
        : "r"(a[0]), "r"(a[1]), "r"(a[2]), "r"(a[3]), "r"(b0), "r"(b1));
}
__device__ __forceinline__ void bsplit(float v, __nv_bfloat16& h, __nv_bfloat16& l) {
    h = __float2bfloat16(v);
    l = __float2bfloat16(v - __bfloat162float(h));
}
__device__ __forceinline__ void cpasync16(uint32_t dst, const void* src, int srcsz) {
    asm volatile("cp.async.cg.shared.global [%0], [%1], 16, %2;"
                 :: "r"(dst), "l"(src), "r"(srcsz));
}
__device__ __forceinline__ void cp_commit() {
    asm volatile("cp.async.commit_group;");
}
__device__ __forceinline__ void cp_wait1() {
    asm volatile("cp.async.wait_group 1;");
}

// ---------------- index dtype detection ---------------------------------------
__global__ void k_detect(const void* __restrict__ ei) {
    __shared__ int s_any;
    if (threadIdx.x == 0) s_any = 0;
    __syncthreads();
    const uint2* p = (const uint2*)ei;
    unsigned any = 0;
    for (int i = threadIdx.x; i < 2048; i += blockDim.x) any |= p[i].y;
    if (any) atomicOr(&s_any, 1);
    __syncthreads();
    if (threadIdx.x == 0) g_is64 = (s_any == 0) ? 1 : 0;
}

__global__ void k_zero_cnt() {
    int t = blockIdx.x * blockDim.x + threadIdx.x;
    if (t < NN) { g_count[t] = 0; g_cursor[t] = 0; }
}

__global__ void k_convert(const void* __restrict__ ei) {
    int t = blockIdx.x * blockDim.x + threadIdx.x;
    if (t >= 2 * EE) return;
    int v;
    if (g_is64) v = (int)((const long long*)ei)[t];
    else        v = ((const int*)ei)[t];
    if (t < EE) g_src[t] = v;
    else { g_dst[t - EE] = v; atomicAdd(&g_count[v], 1); }
}

// ---------------- exclusive scan of g_count -> g_off --------------------------
__global__ void k_s1() {
    int t = blockIdx.x * 512 + threadIdx.x;
    int v = (t < NN) ? g_count[t] : 0;
    __shared__ int sw[16];
    int wid = threadIdx.x >> 5, lid = threadIdx.x & 31;
    int s = v;
#pragma unroll
    for (int o = 16; o > 0; o >>= 1) s += __shfl_down_sync(0xffffffff, s, o);
    if (lid == 0) sw[wid] = s;
    __syncthreads();
    if (wid == 0) {
        int x = (lid < 16) ? sw[lid] : 0;
#pragma unroll
        for (int o = 16; o > 0; o >>= 1) x += __shfl_down_sync(0xffffffff, x, o);
        if (lid == 0) g_bsum[blockIdx.x] = x;
    }
}
__global__ void k_s2() {
    if (threadIdx.x == 0) {
        int run = 0;
        for (int i = 0; i < NB_SCAN; i++) { int v = g_bsum[i]; g_bsum[i] = run; run += v; }
        g_off[NN] = run;
    }
}
__global__ void k_s3() {
    __shared__ int sm[512];
    int t = blockIdx.x * 512 + threadIdx.x;
    int v = (t < NN) ? g_count[t] : 0;
    sm[threadIdx.x] = v;
    __syncthreads();
#pragma unroll
    for (int o = 1; o < 512; o <<= 1) {
        int tmp = (threadIdx.x >= o) ? sm[threadIdx.x - o] : 0;
        __syncthreads();
        sm[threadIdx.x] += tmp;
        __syncthreads();
    }
    if (t < NN) g_off[t] = sm[threadIdx.x] - v + g_bsum[blockIdx.x];
}

__global__ void k_build() {
    int t = blockIdx.x * blockDim.x + threadIdx.x;
    if (t >= EE) return;
    int d = g_dst[t];
    int p = g_off[d] + atomicAdd(&g_cursor[d], 1);
    g_eidx[p] = g_src[t];
}

// ---------------- weight split (runs once, tiny) -------------------------------
__global__ void k_splitw(const float* __restrict__ W1l, const float* __restrict__ W1r,
                         const float* __restrict__ W2l, const float* __restrict__ W2r) {
    int t = blockIdx.x * blockDim.x + threadIdx.x;
    if (t < 256 * 256) {
        int row = t >> 8, k = t & 255;
        float v = (k < 128) ? W1l[row * 128 + k] : W1r[row * 128 + (k - 128)];
        bsplit(v, g_w1h[t], g_w1l[t]);
    } else if (t < 256 * 256 + 128 * 256) {
        int u = t - 256 * 256;
        int row = u >> 8, k = u & 255;
        float v = (row < 64) ? W2l[row * 256 + k] : W2r[(row - 64) * 256 + k];
        bsplit(v, g_w2h[u], g_w2l[u]);
    }
}

// ---------------- layer-1 segmented mean + split: warp per node ----------------
__global__ void k_reduce1(const float* __restrict__ x) {
    int wgl = (blockIdx.x * blockDim.x + threadIdx.x) >> 5;
    int lane = threadIdx.x & 31;
    if (wgl >= NN) return;
    int beg = g_off[wgl], end = g_off[wgl + 1];
    float4 acc = make_float4(0.f, 0.f, 0.f, 0.f);
    for (int base = beg; base < end; base += 32) {
        int rem = end - base;
        int eid = (lane < rem) ? g_eidx[base + lane] : 0;
        int cnt = rem < 32 ? rem : 32;
#pragma unroll 4
        for (int j = 0; j < cnt; j++) {
            int s = __shfl_sync(0xffffffff, eid, j);
            float4 v = ((const float4*)x)[s * 32 + lane];
            acc.x += v.x; acc.y += v.y; acc.z += v.z; acc.w += v.w;
        }
    }
    float inv = 1.0f / fmaxf((float)(end - beg), 1.0f);
    acc.x *= inv; acc.y *= inv; acc.z *= inv; acc.w *= inv;
    if (lane == 0) g_inv[wgl] = inv;

    __nv_bfloat16 h[4], l[4];
    bsplit(acc.x, h[0], l[0]); bsplit(acc.y, h[1], l[1]);
    bsplit(acc.z, h[2], l[2]); bsplit(acc.w, h[3], l[3]);
    *(ushort4*)(g_a1h + wgl * 256 + lane * 4) = *(ushort4*)h;
    *(ushort4*)(g_a1l + wgl * 256 + lane * 4) = *(ushort4*)l;
    float4 xv = ((const float4*)x)[wgl * 32 + lane];
    bsplit(xv.x, h[0], l[0]); bsplit(xv.y, h[1], l[1]);
    bsplit(xv.z, h[2], l[2]); bsplit(xv.w, h[3], l[3]);
    *(ushort4*)(g_a1h + wgl * 256 + 128 + lane * 4) = *(ushort4*)h;
    *(ushort4*)(g_a1l + wgl * 256 + 128 + lane * 4) = *(ushort4*)l;
}

// ======================= pipelined mma.sync bf16x2-split GEMM ================
// MODE 0: h = relu(A1 @ W1^T + b1)   N=256 (grid.y=2)
// MODE 1: pq = H @ W2^T              N=128 (grid.y=1)
// BK=32, double-buffered cp.async. smem stage = {AH,AL,BH,BL} x 8KB -> 64KB.
// 64B rows, swizzle: chunk c (16B) ^= (row>>1)&3.
#define STG   32768
#define OP_AH 0
#define OP_AL 8192
#define OP_BH 16384
#define OP_BL 24576

template <int MODE>
__global__ __launch_bounds__(256) void k_gemm_mma(const float* __restrict__ bias)
{
    extern __shared__ char smem[];
    const uint32_t sb = smem_u32(smem);

    const int tid  = threadIdx.x;
    const int wid  = tid >> 5;
    const int lane = tid & 31;
    const int wm   = wid & 3;
    const int wn   = wid >> 2;
    const int m0   = blockIdx.x * 128;
    const int j0   = blockIdx.y * 128;

    const __nv_bfloat16* Ah = (MODE == 0) ? g_a1h : g_hh;
    const __nv_bfloat16* Al = (MODE == 0) ? g_a1l : g_hl;
    const __nv_bfloat16* Bh = (MODE == 0) ? g_w1h : g_w2h;
    const __nv_bfloat16* Bl = (MODE == 0) ? g_w1l : g_w2l;

    // staging indices: 512 chunks per operand, 2 per thread
    const int row0 = (tid * 2) >> 2;           // via idx=tid*2: rows for i=0,1
    // (recomputed in the loop for clarity)

    float acc[2][8][4];
#pragma unroll
    for (int a = 0; a < 2; a++)
#pragma unroll
        for (int b = 0; b < 8; b++)
#pragma unroll
            for (int c = 0; c < 4; c++) acc[a][b][c] = 0.f;

    const int r8   = lane & 7;
    const int subm = lane >> 3;
    (void)row0;

    // ---- async load of one BK=32 chunk into stage s ---------------------------
    auto load_chunk = [&](int ch, int s) {
        const int kt = ch * 32;
        const uint32_t sbase = sb + s * STG;
#pragma unroll
        for (int i = 0; i < 2; i++) {
            int idx = tid + i * 256;            // 0..511
            int row = idx >> 2;                 // 0..127
            int c   = idx & 3;                  // 16B chunk along k
            uint32_t off = (uint32_t)(row * 64 + ((c ^ ((row >> 1) & 3)) * 16));
            int gr = m0 + row;
            int szA = (gr < NN) ? 16 : 0;
            const __nv_bfloat16* pa = Ah + (size_t)gr * 256 + kt + c * 8;
            const __nv_bfloat16* pl = Al + (size_t)gr * 256 + kt + c * 8;
            if (gr >= NN) { pa = Ah; pl = Al; }   // safe address, zfilled
            cpasync16(sbase + OP_AH + off, pa, szA);
            cpasync16(sbase + OP_AL + off, pl, szA);
            cpasync16(sbase + OP_BH + off, Bh + (size_t)(j0 + row) * 256 + kt + c * 8, 16);
            cpasync16(sbase + OP_BL + off, Bl + (size_t)(j0 + row) * 256 + kt + c * 8, 16);
        }
    };

    load_chunk(0, 0);
    cp_commit();

    for (int ch = 0; ch < 8; ch++) {
        if (ch < 7) load_chunk(ch + 1, (ch + 1) & 1);
        cp_commit();                  // (empty group on last iter)
        cp_wait1();                   // chunk ch's data resident
        __syncthreads();

        const uint32_t sbase = sb + (ch & 1) * STG;
#pragma unroll
        for (int ks = 0; ks < 2; ks++) {
            const int cb = ks * 2;
            uint32_t ahf[2][4], alf[2][4];
#pragma unroll
            for (int tm = 0; tm < 2; tm++) {
                int arow = wm * 32 + tm * 16 + (subm & 1) * 8 + r8;
                int achk = cb + (subm >> 1);
                uint32_t ab = (uint32_t)(arow * 64 + ((achk ^ ((arow >> 1) & 3)) * 16));
                ldsm4(ahf[tm], sbase + OP_AH + ab);
                ldsm4(alf[tm], sbase + OP_AL + ab);
            }
            uint32_t bh[16], bl[16];
#pragma unroll
            for (int g = 0; g < 4; g++) {
                int brow = wn * 64 + g * 16 + (subm >> 1) * 8 + r8;
                int bchk = cb + (subm & 1);
                uint32_t bb = (uint32_t)(brow * 64 + ((bchk ^ ((brow >> 1) & 3)) * 16));
                ldsm4(&bh[g * 4], sbase + OP_BH + bb);
                ldsm4(&bl[g * 4], sbase + OP_BL + bb);
            }
#pragma unroll
            for (int tm = 0; tm < 2; tm++)
#pragma unroll
                for (int tn = 0; tn < 8; tn++) {
                    mma_bf16(acc[tm][tn], ahf[tm], bh[tn * 2], bh[tn * 2 + 1]);
                    mma_bf16(acc[tm][tn], ahf[tm], bl[tn * 2], bl[tn * 2 + 1]);
                    mma_bf16(acc[tm][tn], alf[tm], bh[tn * 2], bh[tn * 2 + 1]);
                }
        }
        __syncthreads();
    }

    // ---- epilogue: MODE0 writes split h; MODE1 writes fp32 pq -----------------
    const int qrow = lane >> 2;
    const int qcol = (lane & 3) * 2;
#pragma unroll
    for (int tm = 0; tm < 2; tm++) {
#pragma unroll
        for (int half = 0; half < 2; half++) {
            int gr = m0 + wm * 32 + tm * 16 + half * 8 + qrow;
            if (gr >= NN) continue;
#pragma unroll
            for (int tn = 0; tn < 8; tn++) {
                int gc = j0 + wn * 64 + tn * 8 + qcol;
                float v0 = acc[tm][tn][half * 2 + 0];
                float v1 = acc[tm][tn][half * 2 + 1];
                if (MODE == 0) {
                    v0 = fmaxf(v0 + bias[gc], 0.f);
                    v1 = fmaxf(v1 + bias[gc + 1], 0.f);
                    __nv_bfloat16 h0, l0, h1, l1;
                    bsplit(v0, h0, l0);
                    bsplit(v1, h1, l1);
                    __nv_bfloat16 hp[2] = {h0, h1}, lp[2] = {l0, l1};
                    *(uint32_t*)(g_hh + gr * 256 + gc) = *(uint32_t*)hp;
                    *(uint32_t*)(g_hl + gr * 256 + gc) = *(uint32_t*)lp;
                } else {
                    *(float2*)(g_pq + gr * (2 * OUTD) + gc) = make_float2(v0, v1);
                }
            }
        }
    }
}

// ---------------- layer-2 segmented mean + epilogue: warp per node ------------
__global__ void k_reduce2(const float* __restrict__ b2, float* __restrict__ out) {
    int wgl = (blockIdx.x * blockDim.x + threadIdx.x) >> 5;
    int lane = threadIdx.x & 31;
    if (wgl >= NN) return;
    int beg = g_off[wgl], end = g_off[wgl + 1];
    float2 acc = make_float2(0.f, 0.f);
    for (int base = beg; base < end; base += 32) {
        int rem = end - base;
        int eid = (lane < rem) ? g_eidx[base + lane] : 0;
        int cnt = rem < 32 ? rem : 32;
#pragma unroll 4
        for (int j = 0; j < cnt; j++) {
            int s = __shfl_sync(0xffffffff, eid, j);
            float2 v = ((const float2*)g_pq)[s * 64 + lane];
            acc.x += v.x; acc.y += v.y;
        }
    }
    float inv = g_inv[wgl];
    float2 q  = ((const float2*)g_pq)[wgl * 64 + 32 + lane];
    float2 bb = ((const float2*)b2)[lane];
    float2 r;
    r.x = fmaf(acc.x, inv, bb.x) + q.x;
    r.y = fmaf(acc.y, inv, bb.y) + q.y;
    ((float2*)out)[wgl * 32 + lane] = r;
}

// ---------------- launch ------------------------------------------------------
extern "C" void kernel_launch(void* const* d_in, const int* in_sizes, int n_in,
                              void* d_out, int out_size) {
    const float* x   = (const float*)d_in[0];
    const void*  ei  = d_in[1];
    const float* W1l = (const float*)d_in[2];
    const float* b1  = (const float*)d_in[3];
    const float* W1r = (const float*)d_in[4];
    const float* W2l = (const float*)d_in[5];
    const float* b2  = (const float*)d_in[6];
    const float* W2r = (const float*)d_in[7];
    float* out = (float*)d_out;

    const int SMEM = 2 * STG;   // 65536
    cudaFuncSetAttribute(k_gemm_mma<0>,
                         cudaFuncAttributeMaxDynamicSharedMemorySize, SMEM);
    cudaFuncSetAttribute(k_gemm_mma<1>,
                         cudaFuncAttributeMaxDynamicSharedMemorySize, SMEM);

    k_detect<<<1, 256>>>(ei);
    k_zero_cnt<<<(NN + 255) / 256, 256>>>();
    k_convert<<<(2 * EE + 255) / 256, 256>>>(ei);
    k_splitw<<<(256 * 256 + 128 * 256 + 255) / 256, 256>>>(W1l, W1r, W2l, W2r);

    k_s1<<<NB_SCAN, 512>>>();
    k_s2<<<1, 32>>>();
    k_s3<<<NB_SCAN, 512>>>();
    k_build<<<(EE + 255) / 256, 256>>>();

    k_reduce1<<<(NN * 32 + 255) / 256, 256>>>(x);

    const int MT = (NN + 127) / 128;   // 782
    k_gemm_mma<0><<<dim3(MT, 2), 256, SMEM>>>(b1);
    k_gemm_mma<1><<<dim3(MT, 1), 256, SMEM>>>(b1);

    k_reduce2<<<(NN * 32 + 255) / 256, 256>>>(b2, out);
}